// round 1
// baseline (speedup 1.0000x reference)
#include <cuda_runtime.h>

// ---------------------------------------------------------------------------
// Leaky CTRNN, 2 layers. B=64, T=512, D_IN=256, H=1024, D_OUT=256, alpha=0.1
//
// Plan:
//   1) gemm_in0: xin0[t][b][h] = x[b,t,:] @ W_in0[h,:] + b0[h]   (parallel)
//   2) 513 step kernels: kernel s computes layer0(t=s) and layer1(t=s-1),
//      which are mutually independent. Each layer's [64,1024]x[1024,1024]
//      GEMM is split over N-tiles (16 cols) and K-chunks (512) for occupancy;
//      the last K-chunk block per tile (atomic ticket) sums partials, applies
//      the leaky update + ReLU, writes states (into d_out) and v scratch.
//   3) gemm_out: output = states1 @ W_out^T + b_out                (parallel)
// ---------------------------------------------------------------------------

namespace {
constexpr int B    = 64;
constexpr int T    = 512;
constexpr int DIN  = 256;
constexpr int H    = 1024;
constexpr int DOUT = 256;
constexpr float ALPHA_F = 0.1f;
constexpr float OMA_F   = 0.9f;

constexpr int BN  = 16;        // n-tile width in step kernel
constexpr int NT  = H / BN;    // 64 tiles
constexpr int KCH = 512;       // k-chunk length
}

// Scratch (allocation-free rule: __device__ globals)
__device__ float    g_xin0[(size_t)T * B * H];   // [t][b][h], 128 MB
__device__ float    g_v0[B * H];
__device__ float    g_v1[B * H];
__device__ float    g_part0[2][B * H];           // layer0 split-K partials
__device__ float    g_part1[4][B * H];           // layer1 split-K partials
__device__ unsigned g_cnt0[NT];                  // zero-init; reset by finisher
__device__ unsigned g_cnt1[NT];

// ---------------------------------------------------------------------------
// Step kernel: grid = nb0 (layer0 blocks) + nb1 (layer1 blocks), 64 thr/block.
// Tile: 64(M) x 16(N), K-chunk 512, BK=32, micro-tile 4x4 per thread.
// ---------------------------------------------------------------------------
__global__ void __launch_bounds__(64)
step_kernel(int s, int nb0,
            const float* __restrict__ Wrec0,
            const float* __restrict__ Win1,
            const float* __restrict__ Wrec1,
            const float* __restrict__ b1,
            float* __restrict__ states0,   // [B][T][H] region of d_out
            float* __restrict__ states1)   // [B][T][H] region of d_out
{
    __shared__ float aS[32 * 64];   // aS[k*64 + m]
    __shared__ float bS[32 * 16];   // bS[k*16 + n]
    __shared__ unsigned s_last;

    const int tid  = threadIdx.x;
    const bool isL0 = ((int)blockIdx.x) < nb0;
    const int idx   = isL0 ? (int)blockIdx.x : ((int)blockIdx.x - nb0);
    const int tile  = idx & (NT - 1);
    const int chunk = idx / NT;
    const int n0    = tile * BN;
    const int t1    = s - 1;           // layer1 timestep

    const float* A = nullptr;          // activations [64 rows, stride T*H]
    const float* W = nullptr;          // weights     [H rows,  stride H]
    int koff = 0;
    int KC;
    if (isL0) {
        KC = 2;
        koff = chunk * KCH;
        W = Wrec0;
        if (s > 0) A = states0 + (size_t)(s - 1) * H;      // fr0[t=s-1]
    } else {
        KC = 4;
        if (chunk < 2) {
            koff = chunk * KCH;
            W = Wrec1;
            if (t1 > 0) A = states1 + (size_t)(t1 - 1) * H; // fr1[t1-1]
        } else {
            koff = (chunk - 2) * KCH;
            W = Win1;
            A = states0 + (size_t)t1 * H;                   // fr0[t1]
        }
    }

    const int tm4 = (tid >> 2) * 4;    // m base: 0..60
    const int tn4 = (tid & 3) * 4;     // n base within tile: 0..12

    float acc[4][4] = {};

    if (A != nullptr) {
        const float* arow = A + (size_t)tid * ((size_t)T * H) + koff;
        const int ln  = tid & 15;
        const int lkb = (tid >> 4) * 8;
        const float* wrow = W + (size_t)(n0 + ln) * H + koff + lkb;

        for (int k0 = 0; k0 < KCH; k0 += 32) {
            float4 av[8];
            #pragma unroll
            for (int c = 0; c < 8; c++)
                av[c] = *(const float4*)(arow + k0 + c * 4);
            float4 bv0 = *(const float4*)(wrow + k0);
            float4 bv1 = *(const float4*)(wrow + k0 + 4);

            __syncthreads();
            #pragma unroll
            for (int c = 0; c < 8; c++) {
                aS[(c * 4 + 0) * 64 + tid] = av[c].x;
                aS[(c * 4 + 1) * 64 + tid] = av[c].y;
                aS[(c * 4 + 2) * 64 + tid] = av[c].z;
                aS[(c * 4 + 3) * 64 + tid] = av[c].w;
            }
            bS[(lkb + 0) * 16 + ln] = bv0.x;
            bS[(lkb + 1) * 16 + ln] = bv0.y;
            bS[(lkb + 2) * 16 + ln] = bv0.z;
            bS[(lkb + 3) * 16 + ln] = bv0.w;
            bS[(lkb + 4) * 16 + ln] = bv1.x;
            bS[(lkb + 5) * 16 + ln] = bv1.y;
            bS[(lkb + 6) * 16 + ln] = bv1.z;
            bS[(lkb + 7) * 16 + ln] = bv1.w;
            __syncthreads();

            #pragma unroll
            for (int kk = 0; kk < 32; kk++) {
                float4 a = *(const float4*)&aS[kk * 64 + tm4];
                float4 b = *(const float4*)&bS[kk * 16 + tn4];
                acc[0][0] += a.x * b.x; acc[0][1] += a.x * b.y;
                acc[0][2] += a.x * b.z; acc[0][3] += a.x * b.w;
                acc[1][0] += a.y * b.x; acc[1][1] += a.y * b.y;
                acc[1][2] += a.y * b.z; acc[1][3] += a.y * b.w;
                acc[2][0] += a.z * b.x; acc[2][1] += a.z * b.y;
                acc[2][2] += a.z * b.z; acc[2][3] += a.z * b.w;
                acc[3][0] += a.w * b.x; acc[3][1] += a.w * b.y;
                acc[3][2] += a.w * b.z; acc[3][3] += a.w * b.w;
            }
        }
    }

    // Write this chunk's partial tile (disjoint slots -> deterministic).
    {
        float* part = isL0 ? g_part0[chunk] : g_part1[chunk];
        #pragma unroll
        for (int i = 0; i < 4; i++) {
            float4 v = make_float4(acc[i][0], acc[i][1], acc[i][2], acc[i][3]);
            *(float4*)&part[(size_t)(tm4 + i) * H + n0 + tn4] = v;
        }
    }

    __threadfence();
    __syncthreads();
    unsigned* cnt = isL0 ? &g_cnt0[tile] : &g_cnt1[tile];
    if (tid == 0) {
        unsigned old = atomicAdd(cnt, 1u);
        s_last = (old == (unsigned)(KC - 1)) ? 1u : 0u;
        if (s_last) *cnt = 0;   // reset for the next launch (all KC arrived)
    }
    __syncthreads();
    if (!s_last) return;
    __threadfence();

    // --- Finisher: sum partials, leaky update, ReLU, write states + v ---
    if (isL0) {
        #pragma unroll
        for (int i = 0; i < 4; i++) {
            const int m = tm4 + i;
            const size_t off = (size_t)m * H + n0 + tn4;
            float4 p0  = *(const float4*)&g_part0[0][off];
            float4 p1  = *(const float4*)&g_part0[1][off];
            float4 xin = *(const float4*)&g_xin0[((size_t)s * B + m) * H + n0 + tn4];
            float4 vp = make_float4(0.f, 0.f, 0.f, 0.f);
            if (s > 0) vp = *(const float4*)&g_v0[off];
            float4 v;
            v.x = OMA_F * vp.x + ALPHA_F * (p0.x + p1.x + xin.x);
            v.y = OMA_F * vp.y + ALPHA_F * (p0.y + p1.y + xin.y);
            v.z = OMA_F * vp.z + ALPHA_F * (p0.z + p1.z + xin.z);
            v.w = OMA_F * vp.w + ALPHA_F * (p0.w + p1.w + xin.w);
            *(float4*)&g_v0[off] = v;
            float4 fr = make_float4(fmaxf(v.x, 0.f), fmaxf(v.y, 0.f),
                                    fmaxf(v.z, 0.f), fmaxf(v.w, 0.f));
            *(float4*)&states0[((size_t)m * T + s) * H + n0 + tn4] = fr;
        }
    } else {
        float4 bb = *(const float4*)&b1[n0 + tn4];
        #pragma unroll
        for (int i = 0; i < 4; i++) {
            const int m = tm4 + i;
            const size_t off = (size_t)m * H + n0 + tn4;
            float4 p0 = *(const float4*)&g_part1[0][off];
            float4 p1 = *(const float4*)&g_part1[1][off];
            float4 p2 = *(const float4*)&g_part1[2][off];
            float4 p3 = *(const float4*)&g_part1[3][off];
            float4 vp = make_float4(0.f, 0.f, 0.f, 0.f);
            if (t1 > 0) vp = *(const float4*)&g_v1[off];
            float4 v;
            v.x = OMA_F * vp.x + ALPHA_F * (p0.x + p1.x + p2.x + p3.x + bb.x);
            v.y = OMA_F * vp.y + ALPHA_F * (p0.y + p1.y + p2.y + p3.y + bb.y);
            v.z = OMA_F * vp.z + ALPHA_F * (p0.z + p1.z + p2.z + p3.z + bb.z);
            v.w = OMA_F * vp.w + ALPHA_F * (p0.w + p1.w + p2.w + p3.w + bb.w);
            *(float4*)&g_v1[off] = v;
            float4 fr = make_float4(fmaxf(v.x, 0.f), fmaxf(v.y, 0.f),
                                    fmaxf(v.z, 0.f), fmaxf(v.w, 0.f));
            *(float4*)&states1[((size_t)m * T + t1) * H + n0 + tn4] = fr;
        }
    }
}

// ---------------------------------------------------------------------------
// gemm_in0: [B*T, DIN] x [H, DIN]^T -> g_xin0[t][b][h] (+ b0)
// Tile 64x64, BK=16, 256 threads, 4x4 micro-tile.
// ---------------------------------------------------------------------------
__global__ void __launch_bounds__(256)
gemm_in0_kernel(const float* __restrict__ x,
                const float* __restrict__ Win0,
                const float* __restrict__ b0)
{
    __shared__ float aS[16 * 64];
    __shared__ float bS[16 * 64];
    const int tid = threadIdx.x;
    const int m0 = blockIdx.x * 64;
    const int n0 = blockIdx.y * 64;
    const int lr = tid >> 2;
    const int lk = (tid & 3) * 4;
    const int tm4 = (tid >> 4) * 4;
    const int tn4 = (tid & 15) * 4;
    float acc[4][4] = {};
    const float* ap = x    + (size_t)(m0 + lr) * DIN + lk;
    const float* bp = Win0 + (size_t)(n0 + lr) * DIN + lk;

    for (int k0 = 0; k0 < DIN; k0 += 16) {
        float4 av = *(const float4*)(ap + k0);
        float4 bv = *(const float4*)(bp + k0);
        __syncthreads();
        aS[(lk + 0) * 64 + lr] = av.x; aS[(lk + 1) * 64 + lr] = av.y;
        aS[(lk + 2) * 64 + lr] = av.z; aS[(lk + 3) * 64 + lr] = av.w;
        bS[(lk + 0) * 64 + lr] = bv.x; bS[(lk + 1) * 64 + lr] = bv.y;
        bS[(lk + 2) * 64 + lr] = bv.z; bS[(lk + 3) * 64 + lr] = bv.w;
        __syncthreads();
        #pragma unroll
        for (int kk = 0; kk < 16; kk++) {
            float4 a = *(const float4*)&aS[kk * 64 + tm4];
            float4 b = *(const float4*)&bS[kk * 64 + tn4];
            acc[0][0] += a.x * b.x; acc[0][1] += a.x * b.y;
            acc[0][2] += a.x * b.z; acc[0][3] += a.x * b.w;
            acc[1][0] += a.y * b.x; acc[1][1] += a.y * b.y;
            acc[1][2] += a.y * b.z; acc[1][3] += a.y * b.w;
            acc[2][0] += a.z * b.x; acc[2][1] += a.z * b.y;
            acc[2][2] += a.z * b.z; acc[2][3] += a.z * b.w;
            acc[3][0] += a.w * b.x; acc[3][1] += a.w * b.y;
            acc[3][2] += a.w * b.z; acc[3][3] += a.w * b.w;
        }
    }

    float4 bb = *(const float4*)&b0[n0 + tn4];
    #pragma unroll
    for (int i = 0; i < 4; i++) {
        int gm = m0 + tm4 + i;
        int bidx = gm >> 9;          // / T
        int tidx = gm & (T - 1);     // % T
        float4 o;
        o.x = acc[i][0] + bb.x; o.y = acc[i][1] + bb.y;
        o.z = acc[i][2] + bb.z; o.w = acc[i][3] + bb.w;
        *(float4*)&g_xin0[((size_t)tidx * B + bidx) * H + n0 + tn4] = o;
    }
}

// ---------------------------------------------------------------------------
// gemm_out: [B*T, H] x [DOUT, H]^T -> out (+ b_out). Same tiling, K=1024.
// ---------------------------------------------------------------------------
__global__ void __launch_bounds__(256)
gemm_out_kernel(const float* __restrict__ states1,
                const float* __restrict__ Wout,
                const float* __restrict__ bout,
                float* __restrict__ out)
{
    __shared__ float aS[16 * 64];
    __shared__ float bS[16 * 64];
    const int tid = threadIdx.x;
    const int m0 = blockIdx.x * 64;
    const int n0 = blockIdx.y * 64;
    const int lr = tid >> 2;
    const int lk = (tid & 3) * 4;
    const int tm4 = (tid >> 4) * 4;
    const int tn4 = (tid & 15) * 4;
    float acc[4][4] = {};
    const float* ap = states1 + (size_t)(m0 + lr) * H + lk;
    const float* bp = Wout    + (size_t)(n0 + lr) * H + lk;

    for (int k0 = 0; k0 < H; k0 += 16) {
        float4 av = *(const float4*)(ap + k0);
        float4 bv = *(const float4*)(bp + k0);
        __syncthreads();
        aS[(lk + 0) * 64 + lr] = av.x; aS[(lk + 1) * 64 + lr] = av.y;
        aS[(lk + 2) * 64 + lr] = av.z; aS[(lk + 3) * 64 + lr] = av.w;
        bS[(lk + 0) * 64 + lr] = bv.x; bS[(lk + 1) * 64 + lr] = bv.y;
        bS[(lk + 2) * 64 + lr] = bv.z; bS[(lk + 3) * 64 + lr] = bv.w;
        __syncthreads();
        #pragma unroll
        for (int kk = 0; kk < 16; kk++) {
            float4 a = *(const float4*)&aS[kk * 64 + tm4];
            float4 b = *(const float4*)&bS[kk * 64 + tn4];
            acc[0][0] += a.x * b.x; acc[0][1] += a.x * b.y;
            acc[0][2] += a.x * b.z; acc[0][3] += a.x * b.w;
            acc[1][0] += a.y * b.x; acc[1][1] += a.y * b.y;
            acc[1][2] += a.y * b.z; acc[1][3] += a.y * b.w;
            acc[2][0] += a.z * b.x; acc[2][1] += a.z * b.y;
            acc[2][2] += a.z * b.z; acc[2][3] += a.z * b.w;
            acc[3][0] += a.w * b.x; acc[3][1] += a.w * b.y;
            acc[3][2] += a.w * b.z; acc[3][3] += a.w * b.w;
        }
    }

    float4 bb = *(const float4*)&bout[n0 + tn4];
    #pragma unroll
    for (int i = 0; i < 4; i++) {
        int gm = m0 + tm4 + i;
        float4 o;
        o.x = acc[i][0] + bb.x; o.y = acc[i][1] + bb.y;
        o.z = acc[i][2] + bb.z; o.w = acc[i][3] + bb.w;
        *(float4*)&out[(size_t)gm * DOUT + n0 + tn4] = o;
    }
}

// ---------------------------------------------------------------------------
extern "C" void kernel_launch(void* const* d_in, const int* in_sizes, int n_in,
                              void* d_out, int out_size)
{
    (void)in_sizes; (void)n_in; (void)out_size;
    const float* x     = (const float*)d_in[0];
    const float* Win0  = (const float*)d_in[1];
    const float* Wrec0 = (const float*)d_in[2];
    const float* b0    = (const float*)d_in[3];
    const float* Win1  = (const float*)d_in[4];
    const float* Wrec1 = (const float*)d_in[5];
    const float* b1    = (const float*)d_in[6];
    const float* Wout  = (const float*)d_in[7];
    const float* bout  = (const float*)d_in[8];

    float* out     = (float*)d_out;                       // [B][T][DOUT]
    float* states0 = out + (size_t)B * T * DOUT;          // [B][T][H]
    float* states1 = states0 + (size_t)B * T * H;         // [B][T][H]

    // 1) Precompute input projection for all timesteps.
    gemm_in0_kernel<<<dim3((B * T) / 64, H / 64), 256>>>(x, Win0, b0);

    // 2) Sequential scan, pipelined: kernel s does layer0(s) + layer1(s-1).
    for (int s = 0; s <= T; s++) {
        const int nb0 = (s < T) ? 2 * NT : 0;   // layer0: 64 tiles x 2 chunks
        const int nb1 = (s >= 1) ? 4 * NT : 0;  // layer1: 64 tiles x 4 chunks
        step_kernel<<<nb0 + nb1, 64>>>(s, nb0, Wrec0, Win1, Wrec1, b1,
                                       states0, states1);
    }

    // 3) Output projection.
    gemm_out_kernel<<<dim3((B * T) / 64, DOUT / 64), 256>>>(states1, Wout,
                                                            bout, out);
}